// round 2
// baseline (speedup 1.0000x reference)
#include <cuda_runtime.h>
#include <math.h>

// Shapes (fixed by the problem):
//   input        : [4096, 32, 8, 8]  f32
//   edge_sources : [32768]           int32
//   e            : [32768, 32, 8, 8] f32
//   w_node/w_edge: [32, 32, 3, 3]    f32
//   out          : [32768, 32, 8, 8] f32
#define CCH   32
#define TILE  2048          // 32*8*8
#define KW    9216          // 32*32*9
#define NNODES 4096

// Scratch for the node-conv output th = conv3x3(input, w_node).
// 4096 * 2048 * 4B = 32 MB (fits in L2 for the gather phase).
__device__ float g_th[(size_t)NNODES * TILE];

// One CTA per item (node or edge). 256 threads: thread t -> (co = t>>3, y = t&7),
// each thread computes one 8-pixel output row for one output channel.
template <bool EDGE>
__global__ __launch_bounds__(256, 4)
void conv3x3_kernel(const float* __restrict__ x,     // [N, 32, 8, 8]
                    const float* __restrict__ w,     // [32, 32, 3, 3]
                    const int*   __restrict__ srcs,  // [E] (EDGE only)
                    float*       __restrict__ out)   // EDGE only
{
    // Weights transposed to w_s[k*32 + co], k = ci*9 + dy*3 + dx.
    // Warp load pattern: same k, 4 distinct co (8-thread broadcast groups) ->
    // 4 distinct consecutive banks, conflict-free.
    __shared__ float w_s[KW];
    __shared__ float e_s[TILE];

    const int b   = blockIdx.x;
    const int tid = threadIdx.x;

    // ---- load weights (transpose [co][k] -> [k][co]) ----
    for (int i = tid; i < KW; i += 256) {
        int co = i / 288;
        int k  = i - co * 288;
        w_s[k * 32 + co] = w[i];
    }
    // ---- load the input tile for this item ----
    {
        const float4* xin = (const float4*)(x + (size_t)b * TILE);
        float4* es4 = (float4*)e_s;
        #pragma unroll
        for (int i = tid; i < TILE / 4; i += 256) es4[i] = xin[i];
    }
    __syncthreads();

    const int co = tid >> 3;   // output channel 0..31
    const int y  = tid & 7;    // output row 0..7

    float acc[8];
    #pragma unroll
    for (int i = 0; i < 8; i++) acc[i] = 0.0f;

    #pragma unroll 4
    for (int ci = 0; ci < CCH; ci++) {
        const float* erow = e_s + ci * 64;
        const float* wci  = w_s + ci * 9 * 32 + co;
        #pragma unroll
        for (int dy = 0; dy < 3; dy++) {
            const int yy = y + dy - 1;
            if (yy < 0 || yy > 7) continue;      // zero padding rows
            // r[i] = e[ci, yy, i-1]; r[0]=r[9]=0 implement x-padding
            float r[10];
            float4 a  = *(const float4*)(erow + yy * 8);
            float4 bb = *(const float4*)(erow + yy * 8 + 4);
            r[0] = 0.0f;
            r[1] = a.x;  r[2] = a.y;  r[3] = a.z;  r[4] = a.w;
            r[5] = bb.x; r[6] = bb.y; r[7] = bb.z; r[8] = bb.w;
            r[9] = 0.0f;
            const float* wp = wci + dy * 3 * 32;
            #pragma unroll
            for (int dx = 0; dx < 3; dx++) {
                const float wv = wp[dx * 32];
                #pragma unroll
                for (int xx = 0; xx < 8; xx++)
                    acc[xx] = fmaf(wv, r[xx + dx], acc[xx]);
            }
        }
    }

    if (EDGE) {
        // gather node conv output, multiply, elu, store
        const int src = srcs[b];
        const float* th = g_th + (size_t)src * TILE + co * 64 + y * 8;
        float4 t0 = *(const float4*)th;
        float4 t1 = *(const float4*)(th + 4);
        float t[8] = {t0.x, t0.y, t0.z, t0.w, t1.x, t1.y, t1.z, t1.w};
        float o[8];
        #pragma unroll
        for (int i = 0; i < 8; i++) {
            float v = t[i] * acc[i];
            o[i] = (v > 0.0f) ? v : expm1f(v);   // elu, alpha=1 (matches jax expm1 path)
        }
        float* op = out + (size_t)b * TILE + co * 64 + y * 8;
        *(float4*)op       = make_float4(o[0], o[1], o[2], o[3]);
        *(float4*)(op + 4) = make_float4(o[4], o[5], o[6], o[7]);
    } else {
        float* op = g_th + (size_t)b * TILE + co * 64 + y * 8;
        *(float4*)op       = make_float4(acc[0], acc[1], acc[2], acc[3]);
        *(float4*)(op + 4) = make_float4(acc[4], acc[5], acc[6], acc[7]);
    }
}

extern "C" void kernel_launch(void* const* d_in, const int* in_sizes, int n_in,
                              void* d_out, int out_size)
{
    const float* input  = (const float*)d_in[0];
    const int*   srcs   = (const int*)  d_in[1];
    const float* e      = (const float*)d_in[2];
    const float* w_node = (const float*)d_in[3];
    const float* w_edge = (const float*)d_in[4];
    float*       out    = (float*)d_out;

    const int n_nodes = in_sizes[0] / TILE;   // 4096
    const int n_edges = in_sizes[2] / TILE;   // 32768

    // 1) node conv -> g_th (scratch)
    conv3x3_kernel<false><<<n_nodes, 256>>>(input, w_node, nullptr, nullptr);
    // 2) edge conv + gather(th) + elu -> out   (same stream: ordered after 1)
    conv3x3_kernel<true><<<n_edges, 256>>>(e, w_edge, srcs, out);
}

// round 3
// speedup vs baseline: 3.9805x; 3.9805x over previous
#include <cuda_runtime.h>
#include <math.h>

// Shapes (fixed):
//   input        : [4096, 32, 8, 8]  f32
//   edge_sources : [32768]           int32
//   e            : [32768, 32, 8, 8] f32
//   w_node/w_edge: [32, 32, 3, 3]    f32
//   out          : [32768, 32, 8, 8] f32
#define CCH    32
#define TILE   2048          // 32*8*8
#define KW     9216          // 32*32*9
#define NNODES 4096

// Scratch: th = conv3x3(input, w_node). 32 MB, L2-resident during gather.
__device__ float g_th[(size_t)NNODES * TILE];

typedef unsigned long long u64;

__device__ __forceinline__ u64 pack2(float lo, float hi) {
    u64 d; asm("mov.b64 %0, {%1, %2};" : "=l"(d) : "f"(lo), "f"(hi)); return d;
}
__device__ __forceinline__ void unpack2(u64 v, float& lo, float& hi) {
    asm("mov.b64 {%0, %1}, %2;" : "=f"(lo), "=f"(hi) : "l"(v));
}
// Packed dual-fp32 FMA (FFMA2) — ptxas never emits this from C++.
__device__ __forceinline__ void fma2(u64& d, u64 a, u64 b, u64 c) {
    asm("fma.rn.f32x2 %0, %1, %2, %3;" : "=l"(d) : "l"(a), "l"(b), "l"(c));
}

__device__ __forceinline__ float elu1(float v) {
    return v > 0.0f ? v : expm1f(v);
}

// One warp per item; lane = output channel. Each lane computes its full 8x8
// output plane with 32 packed accumulators (f32x2).
// E-row loads are warp-uniform LDG.128 (1 sector/warp). Weight LDS are
// lane-consecutive (conflict-free).
template <bool EDGE>
__global__ __launch_bounds__(256, 2)
void conv_kernel(const float* __restrict__ x,     // [N,32,8,8]
                 const float* __restrict__ w,     // [32,32,3,3]
                 const int*   __restrict__ srcs,  // [E]
                 float*       __restrict__ out)
{
    __shared__ float w_s[KW];   // transposed: w_s[k*32+co]
    const int tid = threadIdx.x;

    for (int i = tid; i < KW; i += 256) {
        int co = i / 288;
        int k  = i - co * 288;
        w_s[k * 32 + co] = w[i];
    }
    __syncthreads();

    const int warp = tid >> 5;
    const int co   = tid & 31;
    const int item = blockIdx.x * 8 + warp;

    const float* xi = x + (size_t)item * TILE;

    // A[y][j]: packed output pair (x=2j, 2j+1) of row y
    u64 A[8][4];
    #pragma unroll
    for (int y = 0; y < 8; y++)
        #pragma unroll
        for (int j = 0; j < 4; j++) A[y][j] = 0ULL;

    #pragma unroll 1
    for (int ci = 0; ci < CCH; ci++) {
        // 9 weights for (co, ci), packed (w,w)
        u64 wp[9];
        #pragma unroll
        for (int t = 0; t < 9; t++) {
            float wv = w_s[(ci * 9 + t) * 32 + co];
            wp[t] = pack2(wv, wv);
        }

        const float4* rowp = (const float4*)(xi + ci * 64);

        #pragma unroll
        for (int yy = 0; yy < 8; yy++) {
            float4 a = __ldg(rowp + yy * 2);
            float4 b = __ldg(rowp + yy * 2 + 1);
            // shifted pair sets for the 3 dx taps:
            //   dx=0 -> E0..E3, dx=1 -> O0..O3, dx=2 -> E1..E4
            u64 O0 = pack2(a.x, a.y), O1 = pack2(a.z, a.w);
            u64 O2 = pack2(b.x, b.y), O3 = pack2(b.z, b.w);
            u64 E0 = pack2(0.f, a.x), E1 = pack2(a.y, a.z);
            u64 E2 = pack2(a.w, b.x), E3 = pack2(b.y, b.z);
            u64 E4 = pack2(b.w, 0.f);

            // input row yy feeds output row y = yy + 1 - dy
            #define ROW3(Ay, base)                                   \
                fma2((Ay)[0], wp[(base)+0], E0, (Ay)[0]);            \
                fma2((Ay)[1], wp[(base)+0], E1, (Ay)[1]);            \
                fma2((Ay)[2], wp[(base)+0], E2, (Ay)[2]);            \
                fma2((Ay)[3], wp[(base)+0], E3, (Ay)[3]);            \
                fma2((Ay)[0], wp[(base)+1], O0, (Ay)[0]);            \
                fma2((Ay)[1], wp[(base)+1], O1, (Ay)[1]);            \
                fma2((Ay)[2], wp[(base)+1], O2, (Ay)[2]);            \
                fma2((Ay)[3], wp[(base)+1], O3, (Ay)[3]);            \
                fma2((Ay)[0], wp[(base)+2], E1, (Ay)[0]);            \
                fma2((Ay)[1], wp[(base)+2], E2, (Ay)[1]);            \
                fma2((Ay)[2], wp[(base)+2], E3, (Ay)[2]);            \
                fma2((Ay)[3], wp[(base)+2], E4, (Ay)[3]);

            ROW3(A[yy], 3)                      // dy=1 (y = yy)
            if (yy < 7) { ROW3(A[yy + 1], 0) }  // dy=0 (y = yy+1)
            if (yy > 0) { ROW3(A[yy - 1], 6) }  // dy=2 (y = yy-1)
            #undef ROW3
        }
    }

    if (EDGE) {
        const int src = srcs[item];
        const float4* th4 = (const float4*)(g_th + (size_t)src * TILE + co * 64);
        float4*       op4 = (float4*)(out + (size_t)item * TILE + co * 64);
        #pragma unroll
        for (int y = 0; y < 8; y++) {
            float4 t0 = __ldg(th4 + y * 2);
            float4 t1 = __ldg(th4 + y * 2 + 1);
            float a0,a1,a2,a3,a4,a5,a6,a7;
            unpack2(A[y][0], a0, a1); unpack2(A[y][1], a2, a3);
            unpack2(A[y][2], a4, a5); unpack2(A[y][3], a6, a7);
            op4[y * 2]     = make_float4(elu1(t0.x*a0), elu1(t0.y*a1),
                                         elu1(t0.z*a2), elu1(t0.w*a3));
            op4[y * 2 + 1] = make_float4(elu1(t1.x*a4), elu1(t1.y*a5),
                                         elu1(t1.z*a6), elu1(t1.w*a7));
        }
    } else {
        float4* op4 = (float4*)(g_th + (size_t)item * TILE + co * 64);
        #pragma unroll
        for (int y = 0; y < 8; y++) {
            float a0,a1,a2,a3,a4,a5,a6,a7;
            unpack2(A[y][0], a0, a1); unpack2(A[y][1], a2, a3);
            unpack2(A[y][2], a4, a5); unpack2(A[y][3], a6, a7);
            op4[y * 2]     = make_float4(a0, a1, a2, a3);
            op4[y * 2 + 1] = make_float4(a4, a5, a6, a7);
        }
    }
}

extern "C" void kernel_launch(void* const* d_in, const int* in_sizes, int n_in,
                              void* d_out, int out_size)
{
    const float* input  = (const float*)d_in[0];
    const int*   srcs   = (const int*)  d_in[1];
    const float* e      = (const float*)d_in[2];
    const float* w_node = (const float*)d_in[3];
    const float* w_edge = (const float*)d_in[4];
    float*       out    = (float*)d_out;

    const int n_nodes = in_sizes[0] / TILE;   // 4096
    const int n_edges = in_sizes[2] / TILE;   // 32768

    // 1) node conv -> g_th
    conv_kernel<false><<<n_nodes / 8, 256>>>(input, w_node, nullptr, nullptr);
    // 2) edge conv + gather(th) + elu -> out
    conv_kernel<true><<<n_edges / 8, 256>>>(e, w_edge, srcs, out);
}